// round 1
// baseline (speedup 1.0000x reference)
#include <cuda_runtime.h>

// ---------------------------------------------------------------------------
// SparseCode: 10 Adam iterations of u over strided conv dictionary.
//   act = relu(u - LAM)
//   e   = images - conv_transpose(act, F)        (stride 4, VALID, adjoint)
//   g   = -u + conv(e, F) + act                   (stride 4, VALID)
//   Adam(u, m, v, g, t)
// Output: relu(u_final - LAM), shape [32, 61, 61, 64] fp32.
//
// t=1 is special-cased (u=m=v=0 -> e=images, g=conv(images)) so each replay
// is fully deterministic without a zeroing pass.
// ---------------------------------------------------------------------------

static constexpr float LAM  = 0.1f;
static constexpr float LR   = 0.01f;
static constexpr float B1c  = 0.9f;
static constexpr float B2c  = 0.99f;
static constexpr float OMB1 = 0.1f;    // matches float(1.0 - 0.9) in reference
static constexpr float OMB2 = 0.01f;   // matches float(1.0 - 0.99)
static constexpr float EPSc = 1e-8f;

static constexpr int NB   = 32;
static constexpr int HH   = 256;
static constexpr int WW   = 256;
static constexpr int NC   = 64;
static constexpr int OHW  = 61;        // (256-16)/4 + 1
static constexpr int SPAT = OHW * OHW; // 3721
static constexpr int NOUT = NB * SPAT * NC; // 7,620,608

// scratch (static device allocations only — no cudaMalloc anywhere)
__device__ float g_u[NOUT];
__device__ float g_m[NOUT];
__device__ float g_v[NOUT];
__device__ float g_e[NB * HH * WW];
__device__ float g_Ft[16 * 16 * 64];   // residue-major filter for recon

// ---------------------------------------------------------------------------
// Filter reorg for the transpose-conv gather:
//   g_Ft[((c*4 + i)*4 + ry)*16 + j*4 + rx] = F[ry+4i, rx+4j, c]
// so for fixed (c,i,ry) the 4 rx values at a given j are one aligned float4.
// ---------------------------------------------------------------------------
__global__ void prep_filt_kernel(const float* __restrict__ filt) {
    int i = blockIdx.x * 256 + threadIdx.x;
    if (i < 16 * 16 * 64) {
        int rx = i & 3;
        int j  = (i >> 2) & 3;
        int ry = (i >> 4) & 3;
        int ii = (i >> 6) & 3;
        int c  = i >> 8;
        g_Ft[i] = filt[((ry + 4 * ii) * 16 + (rx + 4 * j)) * 64 + c];
    }
}

// ---------------------------------------------------------------------------
// recon kernel: e[b,p,q] = images[b,p,q] - sum_{i,j,c} act[a-i, g-j, c] *
//                          F[ry+4i, rx+4j, c],  p=4a+ry, q=4g+rx
// Block: 128 threads, tile p:32 (8 a-cells) x q:64 (16 g-cells), one batch b.
// Thread: 2 ry-rows x (2 g-cells x 4 rx) = 16 pixels / 16 accumulators.
// act tile held in smem [c][a][g] (half the channels at a time), zero padded.
// ---------------------------------------------------------------------------
__global__ __launch_bounds__(128) void recon_kernel(const float* __restrict__ images) {
    __shared__ float sAct[32 * 11 * 19];   // 26.75 KB

    const int tid = threadIdx.x;
    const int b   = blockIdx.z;
    const int a0  = blockIdx.y * 8;    // first a-cell of tile
    const int g0  = blockIdx.x * 16;   // first g-cell of tile

    const int ryp = tid >> 6;          // 0..1  -> ry rows {2ryp, 2ryp+1}
    const int a_l = (tid >> 3) & 7;    // 0..7
    const int gp  = tid & 7;           // 0..7  -> g-cells {2gp, 2gp+1}

    float4 accA0 = make_float4(0.f, 0.f, 0.f, 0.f); // ry=2ryp,   gg=0
    float4 accA1 = accA0;                           // ry=2ryp,   gg=1
    float4 accB0 = accA0;                           // ry=2ryp+1, gg=0
    float4 accB1 = accA0;                           // ry=2ryp+1, gg=1

    const float4* __restrict__ Ft4 = (const float4*)g_Ft;

    for (int h = 0; h < 2; h++) {
        __syncthreads();
        // load half the channels of act = relu(u - LAM), zero padded
        for (int idx = tid; idx < 32 * 11 * 19; idx += 128) {
            int c_l  = idx & 31;
            int rest = idx >> 5;
            int a_i  = rest / 19;
            int g_i  = rest - a_i * 19;
            int a = a0 - 3 + a_i;
            int g = g0 - 3 + g_i;
            float val = 0.f;
            if (a >= 0 && a <= 60 && g >= 0 && g <= 60) {
                float uu = g_u[((b * SPAT + a * OHW + g) << 6) + (h << 5) + c_l];
                val = fmaxf(uu - LAM, 0.f);
            }
            sAct[c_l * 209 + a_i * 19 + g_i] = val;
        }
        __syncthreads();

#pragma unroll 1
        for (int c_l = 0; c_l < 32; c_l++) {
            const float* aB = &sAct[c_l * 209 + (a_l + 3) * 19 + 2 * gp + 3];
            const int cbase = ((h << 5) + c_l) << 6;   // c*64 in float4 units
#pragma unroll
            for (int i = 0; i < 4; i++) {
                const float* aR = aB - 19 * i;
                const int fb = cbase + (i << 4) + (ryp << 3); // + ry0*4
#pragma unroll
                for (int j = 0; j < 4; j++) {
                    float av0 = aR[-j];
                    float av1 = aR[1 - j];
                    float4 f0 = Ft4[fb + j];       // ry = 2ryp
                    float4 f1 = Ft4[fb + 4 + j];   // ry = 2ryp+1
                    accA0.x += av0 * f0.x; accA0.y += av0 * f0.y;
                    accA0.z += av0 * f0.z; accA0.w += av0 * f0.w;
                    accA1.x += av1 * f0.x; accA1.y += av1 * f0.y;
                    accA1.z += av1 * f0.z; accA1.w += av1 * f0.w;
                    accB0.x += av0 * f1.x; accB0.y += av0 * f1.y;
                    accB0.z += av0 * f1.z; accB0.w += av0 * f1.w;
                    accB1.x += av1 * f1.x; accB1.y += av1 * f1.y;
                    accB1.z += av1 * f1.z; accB1.w += av1 * f1.w;
                }
            }
        }
    }

    // e = images - recon  (pixels always in-bounds: tiles divide 256 exactly)
    const int p = a0 * 4 + a_l * 4 + 2 * ryp;
    const int q = g0 * 4 + gp * 8;
    const int base = (b * HH + p) * WW + q;

    float4 i00 = *(const float4*)&images[base];
    float4 i01 = *(const float4*)&images[base + 4];
    float4 i10 = *(const float4*)&images[base + WW];
    float4 i11 = *(const float4*)&images[base + WW + 4];

    float4 e00 = make_float4(i00.x - accA0.x, i00.y - accA0.y, i00.z - accA0.z, i00.w - accA0.w);
    float4 e01 = make_float4(i01.x - accA1.x, i01.y - accA1.y, i01.z - accA1.z, i01.w - accA1.w);
    float4 e10 = make_float4(i10.x - accB0.x, i10.y - accB0.y, i10.z - accB0.z, i10.w - accB0.w);
    float4 e11 = make_float4(i11.x - accB1.x, i11.y - accB1.y, i11.z - accB1.z, i11.w - accB1.w);

    *(float4*)&g_e[base]          = e00;
    *(float4*)&g_e[base + 4]      = e01;
    *(float4*)&g_e[base + WW]     = e10;
    *(float4*)&g_e[base + WW + 4] = e11;
}

// ---------------------------------------------------------------------------
// conv + Adam fused kernel.
//   conv_out[b,oy,ox,c] = sum_{ky,kx} src[b, 4oy+ky, 4ox+kx] * F[ky,kx,c]
// t == 1 : src = images, u=m=v treated as 0 (init step)
// t  > 1 : src = g_e,    g = conv_out - u + relu(u-LAM), Adam update
// t == 10: write relu(u_new - LAM) to out instead of storing u/m/v.
// Block: 256 threads, tile oy:8 x ox:16 x 32 channels (half), one batch b.
// Thread: 2 ox x 8 channels = 16 accumulators; sliding img register window.
// ---------------------------------------------------------------------------
__global__ __launch_bounds__(256) void conv_adam_kernel(
    const float* __restrict__ images, const float* __restrict__ filt,
    float* __restrict__ out, int t, float c1, float c2, int use_e)
{
    __shared__ float sF[16 * 16 * 32];  // 32 KB (half the channels)
    __shared__ float sImg[44 * 76];     // 13.4 KB

    const float* __restrict__ src = use_e ? (const float*)g_e : images;

    const int tid = threadIdx.x;
    const int b   = blockIdx.z >> 1;
    const int c0  = (blockIdx.z & 1) * 32;
    const int oy0 = blockIdx.y * 8;
    const int ox0 = blockIdx.x * 16;

    // stage filter slice [ky][kx][32]
    for (int i = tid * 4; i < 16 * 16 * 32; i += 1024) {
        int kxy = i >> 5;
        int c_l = i & 31;
        *(float4*)&sF[i] = *(const float4*)&filt[kxy * 64 + c0 + c_l];
    }
    // stage img tile rows [4*oy0 .. +43], cols [4*ox0 .. +75], clamped to 0
    for (int idx = tid; idx < 44 * 76; idx += 256) {
        int rr = idx / 76;
        int qq = idx - rr * 76;
        int r = 4 * oy0 + rr;
        int q = 4 * ox0 + qq;
        sImg[idx] = (r < HH && q < WW) ? src[(b * HH + r) * WW + q] : 0.f;
    }
    __syncthreads();

    const int cg   = tid & 3;          // channel group: c = c0 + cg*8 .. +7
    const int sp   = tid >> 2;
    const int oy_l = sp >> 3;          // 0..7
    const int oxp  = sp & 7;           // 0..7 -> ox = ox0 + 2*oxp + {0,1}

    float a0[8], a1[8];
#pragma unroll
    for (int k = 0; k < 8; k++) { a0[k] = 0.f; a1[k] = 0.f; }

#pragma unroll 1
    for (int ky = 0; ky < 16; ky++) {
        const float* row = &sImg[(4 * oy_l + ky) * 76 + 8 * oxp];
        float w[20];
#pragma unroll
        for (int x = 0; x < 5; x++) {
            float4 tw = *(const float4*)&row[x * 4];
            w[4 * x + 0] = tw.x; w[4 * x + 1] = tw.y;
            w[4 * x + 2] = tw.z; w[4 * x + 3] = tw.w;
        }
#pragma unroll
        for (int kx = 0; kx < 16; kx++) {
            const float* fp = &sF[(ky * 16 + kx) * 32 + cg * 8];
            float4 fA = *(const float4*)fp;
            float4 fB = *(const float4*)(fp + 4);
            float i0 = w[kx];
            float i1 = w[kx + 4];
            a0[0] += i0 * fA.x; a0[1] += i0 * fA.y; a0[2] += i0 * fA.z; a0[3] += i0 * fA.w;
            a0[4] += i0 * fB.x; a0[5] += i0 * fB.y; a0[6] += i0 * fB.z; a0[7] += i0 * fB.w;
            a1[0] += i1 * fA.x; a1[1] += i1 * fA.y; a1[2] += i1 * fA.z; a1[3] += i1 * fA.w;
            a1[4] += i1 * fB.x; a1[5] += i1 * fB.y; a1[6] += i1 * fB.z; a1[7] += i1 * fB.w;
        }
    }

    const int oy = oy0 + oy_l;
    if (oy > 60) return;
    const int oxa = ox0 + 2 * oxp;

#pragma unroll
    for (int x = 0; x < 2; x++) {
        int ox = oxa + x;
        if (ox > 60) continue;
        int base = ((b * SPAT + oy * OHW + ox) << 6) + c0 + (cg << 3);

        float un[8], mn[8], vn[8];
        if (t == 1) {
#pragma unroll
            for (int k = 0; k < 8; k++) {
                float g = x ? a1[k] : a0[k];
                mn[k] = OMB1 * g;
                vn[k] = OMB2 * g * g;
                un[k] = LR * (mn[k] * c1) / (sqrtf(vn[k] * c2) + EPSc);
            }
        } else {
            float4 u0 = *(const float4*)&g_u[base];
            float4 u1 = *(const float4*)&g_u[base + 4];
            float4 m0 = *(const float4*)&g_m[base];
            float4 m1 = *(const float4*)&g_m[base + 4];
            float4 v0 = *(const float4*)&g_v[base];
            float4 v1 = *(const float4*)&g_v[base + 4];
            float uo[8] = {u0.x, u0.y, u0.z, u0.w, u1.x, u1.y, u1.z, u1.w};
            float mo[8] = {m0.x, m0.y, m0.z, m0.w, m1.x, m1.y, m1.z, m1.w};
            float vo[8] = {v0.x, v0.y, v0.z, v0.w, v1.x, v1.y, v1.z, v1.w};
#pragma unroll
            for (int k = 0; k < 8; k++) {
                float conv = x ? a1[k] : a0[k];
                float act  = fmaxf(uo[k] - LAM, 0.f);
                float g    = conv - uo[k] + act;
                mn[k] = B1c * mo[k] + OMB1 * g;
                vn[k] = B2c * vo[k] + OMB2 * g * g;
                un[k] = uo[k] + LR * (mn[k] * c1) / (sqrtf(vn[k] * c2) + EPSc);
            }
        }

        if (t == 10) {
            float4 o0 = make_float4(fmaxf(un[0] - LAM, 0.f), fmaxf(un[1] - LAM, 0.f),
                                    fmaxf(un[2] - LAM, 0.f), fmaxf(un[3] - LAM, 0.f));
            float4 o1 = make_float4(fmaxf(un[4] - LAM, 0.f), fmaxf(un[5] - LAM, 0.f),
                                    fmaxf(un[6] - LAM, 0.f), fmaxf(un[7] - LAM, 0.f));
            *(float4*)&out[base]     = o0;
            *(float4*)&out[base + 4] = o1;
        } else {
            *(float4*)&g_u[base]     = make_float4(un[0], un[1], un[2], un[3]);
            *(float4*)&g_u[base + 4] = make_float4(un[4], un[5], un[6], un[7]);
            *(float4*)&g_m[base]     = make_float4(mn[0], mn[1], mn[2], mn[3]);
            *(float4*)&g_m[base + 4] = make_float4(mn[4], mn[5], mn[6], mn[7]);
            *(float4*)&g_v[base]     = make_float4(vn[0], vn[1], vn[2], vn[3]);
            *(float4*)&g_v[base + 4] = make_float4(vn[4], vn[5], vn[6], vn[7]);
        }
    }
}

// ---------------------------------------------------------------------------
// launcher: 1 prep + 1 init + 9 x (recon + conv_adam) = 20 launches, all
// default-stream, graph-capturable, allocation-free.
// ---------------------------------------------------------------------------
extern "C" void kernel_launch(void* const* d_in, const int* in_sizes, int n_in,
                              void* d_out, int out_size)
{
    const float* images = (const float*)d_in[0];
    const float* filt   = (const float*)d_in[1];
    if (n_in >= 2 && in_sizes[0] == 16 * 16 * 64) {  // defensive input-order check
        images = (const float*)d_in[1];
        filt   = (const float*)d_in[0];
    }
    float* out = (float*)d_out;

    prep_filt_kernel<<<64, 256>>>(filt);

    dim3 gridC(4, 8, 64);   // ox tiles, oy tiles, b*2 (channel halves)
    dim3 gridR(4, 8, 32);   // q tiles (64px), p tiles (32px), b

    // t = 1: src = images, state implicitly zero
    conv_adam_kernel<<<gridC, 256>>>(images, filt, out, 1, 10.0f, 100.0f, 0);

    for (int t = 2; t <= 10; t++) {
        double c1 = 1.0 / (1.0 - pow(0.9,  (double)t));
        double c2 = 1.0 / (1.0 - pow(0.99, (double)t));
        recon_kernel<<<gridR, 128>>>(images);
        conv_adam_kernel<<<gridC, 256>>>(images, filt, out, t, (float)c1, (float)c2, 1);
    }
}

// round 3
// speedup vs baseline: 1.1493x; 1.1493x over previous
#include <cuda_runtime.h>
#include <math.h>

// ---------------------------------------------------------------------------
// SparseCode: 10 Adam iterations of u over a strided conv dictionary.
//   act = relu(u - LAM)
//   e   = images - conv_transpose(act, F)        (stride 4, VALID, adjoint)
//   g   = -u + conv(e, F) + act                   (stride 4, VALID)
//   Adam(u, m, v, g, t)
// Output: relu(u_final - LAM), shape [32, 61, 61, 64] fp32.
// t=1 special-cased (u=m=v=0 -> e=images) so replays are deterministic.
// ---------------------------------------------------------------------------

static constexpr float LAM  = 0.1f;
static constexpr float LR   = 0.01f;
static constexpr float B1c  = 0.9f;
static constexpr float B2c  = 0.99f;
static constexpr float OMB1 = 0.1f;
static constexpr float OMB2 = 0.01f;
static constexpr float EPSc = 1e-8f;

static constexpr int NB   = 32;
static constexpr int HH   = 256;
static constexpr int WW   = 256;
static constexpr int OHW  = 61;
static constexpr int SPAT = OHW * OHW;
static constexpr int NOUT = NB * SPAT * 64;

__device__ float g_u[NOUT];
__device__ float g_m[NOUT];
__device__ float g_v[NOUT];
__device__ float g_e[NB * HH * WW];
__device__ float g_Ft[16 * 16 * 64];   // residue-major filter for recon

// ---------------------------------------------------------------------------
// g_Ft[((c*4 + i)*4 + ry)*16 + j*4 + rx] = F[ry+4i, rx+4j, c]
// ---------------------------------------------------------------------------
__global__ void prep_filt_kernel(const float* __restrict__ filt) {
    int i = blockIdx.x * 256 + threadIdx.x;
    if (i < 16 * 16 * 64) {
        int rx = i & 3;
        int j  = (i >> 2) & 3;
        int ry = (i >> 4) & 3;
        int ii = (i >> 6) & 3;
        int c  = i >> 8;
        g_Ft[i] = filt[((ry + 4 * ii) * 16 + (rx + 4 * j)) * 64 + c];
    }
}

// ---------------------------------------------------------------------------
// recon: e[b,p,q] = images[b,p,q] - sum_{i,j,c} act[a-i, g-j, c]*F[ry+4i,rx+4j,c]
// Block: 128 thr, tile a:8 (p:32), g:32 (q:128), one batch.
// Thread: 2 ry x 4 g-cells x 4 rx = 32 accumulators.
// Channels processed in 4 groups of 16; act tile + filter quarter in smem.
// ---------------------------------------------------------------------------
__global__ __launch_bounds__(128) void recon_kernel(const float* __restrict__ images) {
    __shared__ __align__(16) float sAct[16 * 11 * 36];   // 24.75 KB
    __shared__ __align__(16) float sFt[4096];            // 16 KB

    const int tid = threadIdx.x;
    const int b   = blockIdx.z;
    const int a0  = blockIdx.y * 8;
    const int g0  = blockIdx.x * 32;

    const int gq  = tid & 7;           // 4 g-cells: g0+4gq .. +3
    const int a_l = (tid >> 3) & 7;
    const int ryp = tid >> 6;          // ry rows {2ryp, 2ryp+1}

    float4 acc0[4], acc1[4];
#pragma unroll
    for (int k = 0; k < 4; k++) {
        acc0[k] = make_float4(0.f, 0.f, 0.f, 0.f);
        acc1[k] = make_float4(0.f, 0.f, 0.f, 0.f);
    }

    const float4* __restrict__ sFt4 = (const float4*)sFt;

    for (int h = 0; h < 4; h++) {
        __syncthreads();
        // stage 16-channel filter slice (contiguous in g_Ft)
        for (int idx = tid * 4; idx < 4096; idx += 512)
            *(float4*)&sFt[idx] = *(const float4*)&g_Ft[h * 4096 + idx];
        // stage act = relu(u - LAM) for 16 channels, zero padded
        for (int idx = tid; idx < 16 * 11 * 35; idx += 128) {
            int c_l  = idx / 385;
            int rest = idx - c_l * 385;
            int a_i  = rest / 35;
            int g_i  = rest - a_i * 35;
            int a = a0 - 3 + a_i;
            int g = g0 - 3 + g_i;
            float val = 0.f;
            if (a >= 0 && a <= 60 && g >= 0 && g <= 60) {
                float uu = g_u[((b * SPAT + a * OHW + g) << 6) + (h << 4) + c_l];
                val = fmaxf(uu - LAM, 0.f);
            }
            sAct[c_l * 396 + a_i * 36 + g_i] = val;
        }
        __syncthreads();

#pragma unroll 1
        for (int c_l = 0; c_l < 16; c_l++) {
            const int crow = c_l * 396;
            const int cb4  = c_l << 6;   // LOCAL channel base in float4 units
#pragma unroll
            for (int i = 0; i < 4; i++) {
                const float* ap = &sAct[crow + (a_l + 3 - i) * 36 + 4 * gq];
                float4 wa = *(const float4*)ap;
                float4 wb = *(const float4*)(ap + 4);
                float w[8] = {wa.x, wa.y, wa.z, wa.w, wb.x, wb.y, wb.z, wb.w};
                const int fb = cb4 + (i << 4) + (ryp << 3);
#pragma unroll
                for (int j = 0; j < 4; j++) {
                    float4 f0 = sFt4[fb + j];       // ry = 2ryp
                    float4 f1 = sFt4[fb + 4 + j];   // ry = 2ryp+1
#pragma unroll
                    for (int k = 0; k < 4; k++) {
                        float av = w[3 + k - j];
                        acc0[k].x += av * f0.x; acc0[k].y += av * f0.y;
                        acc0[k].z += av * f0.z; acc0[k].w += av * f0.w;
                        acc1[k].x += av * f1.x; acc1[k].y += av * f1.y;
                        acc1[k].z += av * f1.z; acc1[k].w += av * f1.w;
                    }
                }
            }
        }
    }

    // e = images - recon (pixels always in-bounds)
    const int p = 4 * (a0 + a_l) + 2 * ryp;
    const int q = 4 * g0 + 16 * gq;
    const int base = (b * HH + p) * WW + q;

#pragma unroll
    for (int k = 0; k < 4; k++) {
        float4 i0 = *(const float4*)&images[base + 4 * k];
        float4 i1 = *(const float4*)&images[base + WW + 4 * k];
        float4 e0 = make_float4(i0.x - acc0[k].x, i0.y - acc0[k].y,
                                i0.z - acc0[k].z, i0.w - acc0[k].w);
        float4 e1 = make_float4(i1.x - acc1[k].x, i1.y - acc1[k].y,
                                i1.z - acc1[k].z, i1.w - acc1[k].w);
        *(float4*)&g_e[base + 4 * k]      = e0;
        *(float4*)&g_e[base + WW + 4 * k] = e1;
    }
}

// ---------------------------------------------------------------------------
// conv + Adam fused.
//   conv_out[b,oy,ox,c] = sum_{ky,kx} src[b,4oy+ky,4ox+kx] * F[ky,kx,c]
// Block: 128 thr, tile oy:8 x ox:32 x 16 channels, one batch.
// Thread: 4 ox x 8 ch = 32 accumulators, 28-wide sliding img window.
// sImg uses a pad-every-32-floats swizzle: phys = c + (c>>5)*4 -> the 8 oxp
// window loads hit 8 distinct bank quads (conflict-free).
// ---------------------------------------------------------------------------
__global__ __launch_bounds__(128) void conv_adam_kernel(
    const float* __restrict__ images, const float* __restrict__ filt,
    float* __restrict__ out, int t, float c1, float c2, int use_e)
{
    __shared__ __align__(16) float sF[16 * 16 * 16];  // 16 KB
    __shared__ __align__(16) float sImg[44 * 156];    // 27.4 KB

    const float* __restrict__ src = use_e ? (const float*)g_e : images;

    const int tid = threadIdx.x;
    const int b   = blockIdx.z >> 2;
    const int c0  = (blockIdx.z & 3) * 16;
    const int oy0 = blockIdx.y * 8;
    const int ox0 = blockIdx.x * 32;

    // stage filter slice [ky*16+kx][16ch]
    for (int i = tid * 4; i < 16 * 16 * 16; i += 512) {
        int kxy = i >> 4;
        int c_l = i & 15;
        *(float4*)&sF[i] = *(const float4*)&filt[kxy * 64 + c0 + c_l];
    }
    // stage img rows [4oy0..+43], cols [4ox0..+139], zero clamped, swizzled
    for (int idx = tid; idx < 44 * 140; idx += 128) {
        int rr = idx / 140;
        int cc = idx - rr * 140;
        int r = 4 * oy0 + rr;
        int q = 4 * ox0 + cc;
        float v = (r < HH && q < WW) ? src[(b * HH + r) * WW + q] : 0.f;
        sImg[rr * 156 + cc + ((cc >> 5) << 2)] = v;
    }
    __syncthreads();

    const int cg   = tid & 1;          // ch subgroup: c0 + 8*cg .. +7
    const int oxp  = (tid >> 1) & 7;   // 4 ox: ox0 + 4*oxp .. +3
    const int oy_l = tid >> 4;         // 0..7

    float4 a[4][2];
#pragma unroll
    for (int x = 0; x < 4; x++) {
        a[x][0] = make_float4(0.f, 0.f, 0.f, 0.f);
        a[x][1] = make_float4(0.f, 0.f, 0.f, 0.f);
    }

#pragma unroll 1
    for (int ky = 0; ky < 16; ky++) {
        const float* row = &sImg[(4 * oy_l + ky) * 156];
        float w[28];
#pragma unroll
        for (int x = 0; x < 7; x++) {
            int cc = 16 * oxp + 4 * x;
            int pc = cc + ((cc >> 5) << 2);
            float4 t4 = *(const float4*)&row[pc];
            w[4 * x + 0] = t4.x; w[4 * x + 1] = t4.y;
            w[4 * x + 2] = t4.z; w[4 * x + 3] = t4.w;
        }
#pragma unroll
        for (int kx = 0; kx < 16; kx++) {
            const float4* fp = (const float4*)&sF[(ky * 16 + kx) * 16 + cg * 8];
            float4 fA = fp[0];
            float4 fB = fp[1];
#pragma unroll
            for (int x = 0; x < 4; x++) {
                float iv = w[kx + 4 * x];
                a[x][0].x += iv * fA.x; a[x][0].y += iv * fA.y;
                a[x][0].z += iv * fA.z; a[x][0].w += iv * fA.w;
                a[x][1].x += iv * fB.x; a[x][1].y += iv * fB.y;
                a[x][1].z += iv * fB.z; a[x][1].w += iv * fB.w;
            }
        }
    }

    const int oy = oy0 + oy_l;
    if (oy > 60) return;

#pragma unroll
    for (int x = 0; x < 4; x++) {
        int ox = ox0 + 4 * oxp + x;
        if (ox > 60) continue;
        int base = ((b * SPAT + oy * OHW + ox) << 6) + c0 + (cg << 3);

        float cv[8] = {a[x][0].x, a[x][0].y, a[x][0].z, a[x][0].w,
                       a[x][1].x, a[x][1].y, a[x][1].z, a[x][1].w};
        float un[8], mn[8], vn[8];
        if (t == 1) {
#pragma unroll
            for (int k = 0; k < 8; k++) {
                float g = cv[k];
                mn[k] = OMB1 * g;
                vn[k] = OMB2 * g * g;
                un[k] = LR * (mn[k] * c1) / (sqrtf(vn[k] * c2) + EPSc);
            }
        } else {
            float4 u0 = *(const float4*)&g_u[base];
            float4 u1 = *(const float4*)&g_u[base + 4];
            float4 m0 = *(const float4*)&g_m[base];
            float4 m1 = *(const float4*)&g_m[base + 4];
            float4 v0 = *(const float4*)&g_v[base];
            float4 v1 = *(const float4*)&g_v[base + 4];
            float uo[8] = {u0.x, u0.y, u0.z, u0.w, u1.x, u1.y, u1.z, u1.w};
            float mo[8] = {m0.x, m0.y, m0.z, m0.w, m1.x, m1.y, m1.z, m1.w};
            float vo[8] = {v0.x, v0.y, v0.z, v0.w, v1.x, v1.y, v1.z, v1.w};
#pragma unroll
            for (int k = 0; k < 8; k++) {
                float act = fmaxf(uo[k] - LAM, 0.f);
                float g   = cv[k] - uo[k] + act;
                mn[k] = B1c * mo[k] + OMB1 * g;
                vn[k] = B2c * vo[k] + OMB2 * g * g;
                un[k] = uo[k] + LR * (mn[k] * c1) / (sqrtf(vn[k] * c2) + EPSc);
            }
        }

        if (t == 10) {
            float4 o0 = make_float4(fmaxf(un[0] - LAM, 0.f), fmaxf(un[1] - LAM, 0.f),
                                    fmaxf(un[2] - LAM, 0.f), fmaxf(un[3] - LAM, 0.f));
            float4 o1 = make_float4(fmaxf(un[4] - LAM, 0.f), fmaxf(un[5] - LAM, 0.f),
                                    fmaxf(un[6] - LAM, 0.f), fmaxf(un[7] - LAM, 0.f));
            *(float4*)&out[base]     = o0;
            *(float4*)&out[base + 4] = o1;
        } else {
            *(float4*)&g_u[base]     = make_float4(un[0], un[1], un[2], un[3]);
            *(float4*)&g_u[base + 4] = make_float4(un[4], un[5], un[6], un[7]);
            *(float4*)&g_m[base]     = make_float4(mn[0], mn[1], mn[2], mn[3]);
            *(float4*)&g_m[base + 4] = make_float4(mn[4], mn[5], mn[6], mn[7]);
            *(float4*)&g_v[base]     = make_float4(vn[0], vn[1], vn[2], vn[3]);
            *(float4*)&g_v[base + 4] = make_float4(vn[4], vn[5], vn[6], vn[7]);
        }
    }
}

// ---------------------------------------------------------------------------
// launcher: 1 prep + 1 init + 9 x (recon + conv_adam), all graph-capturable.
// ---------------------------------------------------------------------------
extern "C" void kernel_launch(void* const* d_in, const int* in_sizes, int n_in,
                              void* d_out, int out_size)
{
    const float* images = (const float*)d_in[0];
    const float* filt   = (const float*)d_in[1];
    if (n_in >= 2 && in_sizes[0] == 16 * 16 * 64) {
        images = (const float*)d_in[1];
        filt   = (const float*)d_in[0];
    }
    float* out = (float*)d_out;

    prep_filt_kernel<<<64, 256>>>(filt);

    dim3 gridC(2, 8, 128);  // ox tiles, oy tiles, b*4 channel quarters
    dim3 gridR(2, 8, 32);   // q tiles (128px), p tiles (32px), b

    conv_adam_kernel<<<gridC, 128>>>(images, filt, out, 1, 10.0f, 100.0f, 0);

    for (int t = 2; t <= 10; t++) {
        double c1 = 1.0 / (1.0 - pow(0.9,  (double)t));
        double c2 = 1.0 / (1.0 - pow(0.99, (double)t));
        recon_kernel<<<gridR, 128>>>(images);
        conv_adam_kernel<<<gridC, 128>>>(images, filt, out, t, (float)c1, (float)c2, 1);
    }
}

// round 4
// speedup vs baseline: 1.3397x; 1.1656x over previous
#include <cuda_runtime.h>
#include <math.h>

// ---------------------------------------------------------------------------
// SparseCode: 10 Adam iterations of u over a strided conv dictionary.
// This round: all inner-loop math moved to packed fma.rn.f32x2 (FFMA2),
// which ptxas never emits from C++ — 2 fp32 FMAs per issue slot, bit-exact.
// ---------------------------------------------------------------------------

static constexpr float LAM  = 0.1f;
static constexpr float LR   = 0.01f;
static constexpr float B1c  = 0.9f;
static constexpr float B2c  = 0.99f;
static constexpr float OMB1 = 0.1f;
static constexpr float OMB2 = 0.01f;
static constexpr float EPSc = 1e-8f;

static constexpr int NB   = 32;
static constexpr int HH   = 256;
static constexpr int WW   = 256;
static constexpr int OHW  = 61;
static constexpr int SPAT = OHW * OHW;
static constexpr int NOUT = NB * SPAT * 64;

typedef unsigned long long ull;

__device__ __forceinline__ ull bcast2(float v) {
    ull r; asm("mov.b64 %0, {%1, %1};" : "=l"(r) : "f"(v)); return r;
}
__device__ __forceinline__ ull ffma2(ull a, ull b, ull c) {
    ull d; asm("fma.rn.f32x2 %0, %1, %2, %3;" : "=l"(d) : "l"(a), "l"(b), "l"(c));
    return d;
}
__device__ __forceinline__ float2 unpack2(ull v) {
    float2 r; asm("mov.b64 {%0, %1}, %2;" : "=f"(r.x), "=f"(r.y) : "l"(v));
    return r;
}

__device__ float g_u[NOUT];
__device__ float g_m[NOUT];
__device__ float g_v[NOUT];
__device__ float g_e[NB * HH * WW];
__device__ float g_Ft[16 * 16 * 64];   // residue-major filter for recon

// g_Ft[((c*4 + i)*4 + ry)*16 + j*4 + rx] = F[ry+4i, rx+4j, c]
__global__ void prep_filt_kernel(const float* __restrict__ filt) {
    int i = blockIdx.x * 256 + threadIdx.x;
    if (i < 16 * 16 * 64) {
        int rx = i & 3;
        int j  = (i >> 2) & 3;
        int ry = (i >> 4) & 3;
        int ii = (i >> 6) & 3;
        int c  = i >> 8;
        g_Ft[i] = filt[((ry + 4 * ii) * 16 + (rx + 4 * j)) * 64 + c];
    }
}

// ---------------------------------------------------------------------------
// recon: e[b,p,q] = images[b,p,q] - sum_{i,j,c} act[a-i,g-j,c]*F[ry+4i,rx+4j,c]
// Block 128 thr, tile a:8 (p:32) x g:32 (q:128), one batch.
// Thread: 2 ry x 4 g-cells x 4 rx = 32 scalar acc -> 16 f32x2 acc.
// ---------------------------------------------------------------------------
__global__ __launch_bounds__(128) void recon_kernel(const float* __restrict__ images) {
    __shared__ __align__(16) float sAct[16 * 11 * 36];   // 24.75 KB
    __shared__ __align__(16) float sFt[4096];            // 16 KB

    const int tid = threadIdx.x;
    const int b   = blockIdx.z;
    const int a0  = blockIdx.y * 8;
    const int g0  = blockIdx.x * 32;

    const int gq  = tid & 7;           // 4 g-cells: g0+4gq .. +3
    const int a_l = (tid >> 3) & 7;
    const int ryp = tid >> 6;          // ry rows {2ryp, 2ryp+1}

    // A0/A1: [g-cell k][rx-pair] packed accumulators
    ull A0[4][2], A1[4][2];
#pragma unroll
    for (int k = 0; k < 4; k++) {
        A0[k][0] = 0ull; A0[k][1] = 0ull;
        A1[k][0] = 0ull; A1[k][1] = 0ull;
    }

    const ulonglong2* __restrict__ sFtp = (const ulonglong2*)sFt;

    for (int h = 0; h < 4; h++) {
        __syncthreads();
        for (int idx = tid * 4; idx < 4096; idx += 512)
            *(float4*)&sFt[idx] = *(const float4*)&g_Ft[h * 4096 + idx];
        for (int idx = tid; idx < 16 * 11 * 35; idx += 128) {
            int c_l  = idx / 385;
            int rest = idx - c_l * 385;
            int a_i  = rest / 35;
            int g_i  = rest - a_i * 35;
            int a = a0 - 3 + a_i;
            int g = g0 - 3 + g_i;
            float val = 0.f;
            if (a >= 0 && a <= 60 && g >= 0 && g <= 60) {
                float uu = g_u[((b * SPAT + a * OHW + g) << 6) + (h << 4) + c_l];
                val = fmaxf(uu - LAM, 0.f);
            }
            sAct[c_l * 396 + a_i * 36 + g_i] = val;
        }
        __syncthreads();

#pragma unroll 1
        for (int c_l = 0; c_l < 16; c_l++) {
            const int crow = c_l * 396;
            const int cb4  = c_l << 6;   // local channel base, float4 units
#pragma unroll
            for (int i = 0; i < 4; i++) {
                const float* ap = &sAct[crow + (a_l + 3 - i) * 36 + 4 * gq];
                float4 wa = *(const float4*)ap;
                float4 wb = *(const float4*)(ap + 4);
                // broadcast-packed act window (indices 0..6 used)
                ull wp[7];
                wp[0] = bcast2(wa.x); wp[1] = bcast2(wa.y);
                wp[2] = bcast2(wa.z); wp[3] = bcast2(wa.w);
                wp[4] = bcast2(wb.x); wp[5] = bcast2(wb.y);
                wp[6] = bcast2(wb.z);
                const int fb = cb4 + (i << 4) + (ryp << 3);
#pragma unroll
                for (int j = 0; j < 4; j++) {
                    ulonglong2 f0 = sFtp[fb + j];       // ry = 2ryp, rx pairs
                    ulonglong2 f1 = sFtp[fb + 4 + j];   // ry = 2ryp+1
#pragma unroll
                    for (int k = 0; k < 4; k++) {
                        ull av = wp[3 + k - j];
                        A0[k][0] = ffma2(av, f0.x, A0[k][0]);
                        A0[k][1] = ffma2(av, f0.y, A0[k][1]);
                        A1[k][0] = ffma2(av, f1.x, A1[k][0]);
                        A1[k][1] = ffma2(av, f1.y, A1[k][1]);
                    }
                }
            }
        }
    }

    const int p = 4 * (a0 + a_l) + 2 * ryp;
    const int q = 4 * g0 + 16 * gq;
    const int base = (b * HH + p) * WW + q;

#pragma unroll
    for (int k = 0; k < 4; k++) {
        float2 r0a = unpack2(A0[k][0]), r0b = unpack2(A0[k][1]);
        float2 r1a = unpack2(A1[k][0]), r1b = unpack2(A1[k][1]);
        float4 i0 = *(const float4*)&images[base + 4 * k];
        float4 i1 = *(const float4*)&images[base + WW + 4 * k];
        float4 e0 = make_float4(i0.x - r0a.x, i0.y - r0a.y, i0.z - r0b.x, i0.w - r0b.y);
        float4 e1 = make_float4(i1.x - r1a.x, i1.y - r1a.y, i1.z - r1b.x, i1.w - r1b.y);
        *(float4*)&g_e[base + 4 * k]      = e0;
        *(float4*)&g_e[base + WW + 4 * k] = e1;
    }
}

// ---------------------------------------------------------------------------
// conv + Adam fused.
// Block 128 thr, tile oy:8 x ox:32 x 16 channels, one batch.
// Thread: 4 ox x 8 ch = 32 scalar acc -> 16 f32x2 acc (ch pairs).
// ---------------------------------------------------------------------------
__global__ __launch_bounds__(128) void conv_adam_kernel(
    const float* __restrict__ images, const float* __restrict__ filt,
    float* __restrict__ out, int t, float c1, float c2, int use_e)
{
    __shared__ __align__(16) float sF[16 * 16 * 16];  // 16 KB
    __shared__ __align__(16) float sImg[44 * 156];    // 27.4 KB

    const float* __restrict__ src = use_e ? (const float*)g_e : images;

    const int tid = threadIdx.x;
    const int b   = blockIdx.z >> 2;
    const int c0  = (blockIdx.z & 3) * 16;
    const int oy0 = blockIdx.y * 8;
    const int ox0 = blockIdx.x * 32;

    for (int i = tid * 4; i < 16 * 16 * 16; i += 512) {
        int kxy = i >> 4;
        int c_l = i & 15;
        *(float4*)&sF[i] = *(const float4*)&filt[kxy * 64 + c0 + c_l];
    }
    for (int idx = tid; idx < 44 * 140; idx += 128) {
        int rr = idx / 140;
        int cc = idx - rr * 140;
        int r = 4 * oy0 + rr;
        int q = 4 * ox0 + cc;
        float v = (r < HH && q < WW) ? src[(b * HH + r) * WW + q] : 0.f;
        sImg[rr * 156 + cc + ((cc >> 5) << 2)] = v;
    }
    __syncthreads();

    const int cg   = tid & 1;          // ch subgroup: c0 + 8*cg .. +7
    const int oxp  = (tid >> 1) & 7;   // 4 ox: ox0 + 4*oxp .. +3
    const int oy_l = tid >> 4;         // 0..7

    ull A[4][4];                        // [ox][ch-pair]
#pragma unroll
    for (int x = 0; x < 4; x++)
#pragma unroll
        for (int p = 0; p < 4; p++) A[x][p] = 0ull;

#pragma unroll 1
    for (int ky = 0; ky < 16; ky++) {
        const float* row = &sImg[(4 * oy_l + ky) * 156];
        float w[28];
#pragma unroll
        for (int x = 0; x < 7; x++) {
            int cc = 16 * oxp + 4 * x;
            int pc = cc + ((cc >> 5) << 2);
            float4 t4 = *(const float4*)&row[pc];
            w[4 * x + 0] = t4.x; w[4 * x + 1] = t4.y;
            w[4 * x + 2] = t4.z; w[4 * x + 3] = t4.w;
        }
#pragma unroll
        for (int kx = 0; kx < 16; kx++) {
            const ulonglong2* fp = (const ulonglong2*)&sF[(ky * 16 + kx) * 16 + cg * 8];
            ulonglong2 fa = fp[0];   // ch pairs 0,1
            ulonglong2 fb = fp[1];   // ch pairs 2,3
#pragma unroll
            for (int x = 0; x < 4; x++) {
                ull iv = bcast2(w[kx + 4 * x]);
                A[x][0] = ffma2(iv, fa.x, A[x][0]);
                A[x][1] = ffma2(iv, fa.y, A[x][1]);
                A[x][2] = ffma2(iv, fb.x, A[x][2]);
                A[x][3] = ffma2(iv, fb.y, A[x][3]);
            }
        }
    }

    const int oy = oy0 + oy_l;
    if (oy > 60) return;

#pragma unroll
    for (int x = 0; x < 4; x++) {
        int ox = ox0 + 4 * oxp + x;
        if (ox > 60) continue;
        int base = ((b * SPAT + oy * OHW + ox) << 6) + c0 + (cg << 3);

        float cv[8];
#pragma unroll
        for (int p = 0; p < 4; p++) {
            float2 r = unpack2(A[x][p]);
            cv[2 * p]     = r.x;
            cv[2 * p + 1] = r.y;
        }
        float un[8], mn[8], vn[8];
        if (t == 1) {
#pragma unroll
            for (int k = 0; k < 8; k++) {
                float g = cv[k];
                mn[k] = OMB1 * g;
                vn[k] = OMB2 * g * g;
                un[k] = LR * (mn[k] * c1) / (sqrtf(vn[k] * c2) + EPSc);
            }
        } else {
            float4 u0 = *(const float4*)&g_u[base];
            float4 u1 = *(const float4*)&g_u[base + 4];
            float4 m0 = *(const float4*)&g_m[base];
            float4 m1 = *(const float4*)&g_m[base + 4];
            float4 v0 = *(const float4*)&g_v[base];
            float4 v1 = *(const float4*)&g_v[base + 4];
            float uo[8] = {u0.x, u0.y, u0.z, u0.w, u1.x, u1.y, u1.z, u1.w};
            float mo[8] = {m0.x, m0.y, m0.z, m0.w, m1.x, m1.y, m1.z, m1.w};
            float vo[8] = {v0.x, v0.y, v0.z, v0.w, v1.x, v1.y, v1.z, v1.w};
#pragma unroll
            for (int k = 0; k < 8; k++) {
                float act = fmaxf(uo[k] - LAM, 0.f);
                float g   = cv[k] - uo[k] + act;
                mn[k] = B1c * mo[k] + OMB1 * g;
                vn[k] = B2c * vo[k] + OMB2 * g * g;
                un[k] = uo[k] + LR * (mn[k] * c1) / (sqrtf(vn[k] * c2) + EPSc);
            }
        }

        if (t == 10) {
            float4 o0 = make_float4(fmaxf(un[0] - LAM, 0.f), fmaxf(un[1] - LAM, 0.f),
                                    fmaxf(un[2] - LAM, 0.f), fmaxf(un[3] - LAM, 0.f));
            float4 o1 = make_float4(fmaxf(un[4] - LAM, 0.f), fmaxf(un[5] - LAM, 0.f),
                                    fmaxf(un[6] - LAM, 0.f), fmaxf(un[7] - LAM, 0.f));
            *(float4*)&out[base]     = o0;
            *(float4*)&out[base + 4] = o1;
        } else {
            *(float4*)&g_u[base]     = make_float4(un[0], un[1], un[2], un[3]);
            *(float4*)&g_u[base + 4] = make_float4(un[4], un[5], un[6], un[7]);
            *(float4*)&g_m[base]     = make_float4(mn[0], mn[1], mn[2], mn[3]);
            *(float4*)&g_m[base + 4] = make_float4(mn[4], mn[5], mn[6], mn[7]);
            *(float4*)&g_v[base]     = make_float4(vn[0], vn[1], vn[2], vn[3]);
            *(float4*)&g_v[base + 4] = make_float4(vn[4], vn[5], vn[6], vn[7]);
        }
    }
}

// ---------------------------------------------------------------------------
// launcher: 1 prep + 1 init + 9 x (recon + conv_adam), graph-capturable.
// ---------------------------------------------------------------------------
extern "C" void kernel_launch(void* const* d_in, const int* in_sizes, int n_in,
                              void* d_out, int out_size)
{
    const float* images = (const float*)d_in[0];
    const float* filt   = (const float*)d_in[1];
    if (n_in >= 2 && in_sizes[0] == 16 * 16 * 64) {
        images = (const float*)d_in[1];
        filt   = (const float*)d_in[0];
    }
    float* out = (float*)d_out;

    prep_filt_kernel<<<64, 256>>>(filt);

    dim3 gridC(2, 8, 128);  // ox tiles, oy tiles, b*4 channel quarters
    dim3 gridR(2, 8, 32);   // q tiles (128px), p tiles (32px), b

    conv_adam_kernel<<<gridC, 128>>>(images, filt, out, 1, 10.0f, 100.0f, 0);

    for (int t = 2; t <= 10; t++) {
        double c1 = 1.0 / (1.0 - pow(0.9,  (double)t));
        double c2 = 1.0 / (1.0 - pow(0.99, (double)t));
        recon_kernel<<<gridR, 128>>>(images);
        conv_adam_kernel<<<gridC, 128>>>(images, filt, out, t, (float)c1, (float)c2, 1);
    }
}

// round 5
// speedup vs baseline: 1.5026x; 1.1216x over previous
#include <cuda_runtime.h>
#include <math.h>

// ---------------------------------------------------------------------------
// SparseCode: 10 Adam iterations of u over a strided conv dictionary.
// FFMA2 (fma.rn.f32x2) everywhere in the hot loops; this round recon is
// retiled for full-chip fill (1024 blocks) + 37.5% occupancy + conflict-free
// smem phases.
// ---------------------------------------------------------------------------

static constexpr float LAM  = 0.1f;
static constexpr float LR   = 0.01f;
static constexpr float B1c  = 0.9f;
static constexpr float B2c  = 0.99f;
static constexpr float OMB1 = 0.1f;
static constexpr float OMB2 = 0.01f;
static constexpr float EPSc = 1e-8f;

static constexpr int NB   = 32;
static constexpr int HH   = 256;
static constexpr int WW   = 256;
static constexpr int OHW  = 61;
static constexpr int SPAT = OHW * OHW;
static constexpr int NOUT = NB * SPAT * 64;

typedef unsigned long long ull;

__device__ __forceinline__ ull bcast2(float v) {
    ull r; asm("mov.b64 %0, {%1, %1};" : "=l"(r) : "f"(v)); return r;
}
__device__ __forceinline__ ull ffma2(ull a, ull b, ull c) {
    ull d; asm("fma.rn.f32x2 %0, %1, %2, %3;" : "=l"(d) : "l"(a), "l"(b), "l"(c));
    return d;
}
__device__ __forceinline__ float2 unpack2(ull v) {
    float2 r; asm("mov.b64 {%0, %1}, %2;" : "=f"(r.x), "=f"(r.y) : "l"(v));
    return r;
}

__device__ float g_u[NOUT];
__device__ float g_m[NOUT];
__device__ float g_v[NOUT];
__device__ float g_e[NB * HH * WW];
// residue-major filter, ry-stride padded 16->20 words for bank-phase freedom:
// g_Ft2[((c*4 + i)*4 + ry)*20 + j*4 + rx] = F[ry+4i, rx+4j, c]
__device__ float g_Ft2[64 * 4 * 4 * 20];

__global__ void prep_filt_kernel(const float* __restrict__ filt) {
    int i = blockIdx.x * 256 + threadIdx.x;
    if (i < 16 * 16 * 64) {
        int rx = i & 3;
        int j  = (i >> 2) & 3;
        int ry = (i >> 4) & 3;
        int ii = (i >> 6) & 3;
        int c  = i >> 8;
        g_Ft2[((c * 4 + ii) * 4 + ry) * 20 + j * 4 + rx] =
            filt[((ry + 4 * ii) * 16 + (rx + 4 * j)) * 64 + c];
    }
}

// ---------------------------------------------------------------------------
// recon: e[b,p,q] = images[b,p,q] - sum_{i,j,c} act[a-i,g-j,c]*F[ry+4i,rx+4j,c]
// Block 128 thr, tile a:8 (p:32) x g:16 (q:64), one batch. Grid 4x8x32 = 1024.
// Thread: 1 ry x 4 g-cells x 4 rx = 16 px, 8 f32x2 accumulators.
// tid = rf(b0-1) | gq(b2-3) | a_l(b4-6): quarter-warp phases see only 2
// distinct act addresses (broadcast) and 4 bank-disjoint filter chunks.
// ---------------------------------------------------------------------------
__global__ __launch_bounds__(128, 6) void recon_kernel(const float* __restrict__ images) {
    __shared__ __align__(16) float sAct[16 * 220];   // 16ch x 11a x 20g = 14.08 KB
    __shared__ __align__(16) float sFt[5120];        // 16ch x 4i x 4ry x 20 = 20 KB

    const int tid = threadIdx.x;
    const int b   = blockIdx.z;
    const int a0  = blockIdx.y * 8;
    const int g0  = blockIdx.x * 16;

    const int rf  = tid & 3;           // ry row
    const int gq  = (tid >> 2) & 3;    // 4 g-cells: g0+4gq .. +3
    const int a_l = tid >> 4;          // 0..7

    ull A[4][2];                        // [g-cell k][rx-pair]
#pragma unroll
    for (int k = 0; k < 4; k++) { A[k][0] = 0ull; A[k][1] = 0ull; }

    const ulonglong2* __restrict__ sFtp = (const ulonglong2*)sFt;

    for (int h = 0; h < 4; h++) {
        __syncthreads();
        // stage 16-channel padded filter slice (contiguous in g_Ft2)
        for (int idx = tid * 4; idx < 5120; idx += 512)
            *(float4*)&sFt[idx] = *(const float4*)&g_Ft2[h * 5120 + idx];
        // stage act = relu(u - LAM), channel-fastest for coalesced g_u reads
        for (int idx = tid; idx < 16 * 209; idx += 128) {
            int c_l  = idx & 15;
            int rest = idx >> 4;        // 0..208 = a_i*19 + g_i
            int a_i  = rest / 19;
            int g_i  = rest - a_i * 19;
            int a = a0 - 3 + a_i;
            int g = g0 - 3 + g_i;
            float val = 0.f;
            if (a >= 0 && a <= 60 && g >= 0 && g <= 60) {
                float uu = g_u[((b * SPAT + a * OHW + g) << 6) + (h << 4) + c_l];
                val = fmaxf(uu - LAM, 0.f);
            }
            sAct[c_l * 220 + a_i * 20 + g_i] = val;
        }
        __syncthreads();

#pragma unroll 1
        for (int c_l = 0; c_l < 16; c_l++) {
            const int crow = c_l * 220;
#pragma unroll
            for (int i = 0; i < 4; i++) {
                const float* ap = &sAct[crow + (a_l + 3 - i) * 20 + 4 * gq];
                float4 wa = *(const float4*)ap;
                float4 wb = *(const float4*)(ap + 4);
                ull wp[7];
                wp[0] = bcast2(wa.x); wp[1] = bcast2(wa.y);
                wp[2] = bcast2(wa.z); wp[3] = bcast2(wa.w);
                wp[4] = bcast2(wb.x); wp[5] = bcast2(wb.y);
                wp[6] = bcast2(wb.z);
                // float4-granular filter index: ((c*4+i)*4+rf)*5 + j
                const int f4b = ((c_l * 4 + i) * 4 + rf) * 5;
#pragma unroll
                for (int j = 0; j < 4; j++) {
                    ulonglong2 f = sFtp[f4b + j];   // rx pairs for (rf, j)
#pragma unroll
                    for (int k = 0; k < 4; k++) {
                        ull av = wp[3 + k - j];
                        A[k][0] = ffma2(av, f.x, A[k][0]);
                        A[k][1] = ffma2(av, f.y, A[k][1]);
                    }
                }
            }
        }
    }

    // e = images - recon ; one pixel row per thread, 16 contiguous pixels
    const int p = 4 * (a0 + a_l) + rf;
    const int q = 4 * g0 + 16 * gq;
    const int base = (b * HH + p) * WW + q;

#pragma unroll
    for (int k = 0; k < 4; k++) {
        float2 ra = unpack2(A[k][0]), rb = unpack2(A[k][1]);
        float4 iv = *(const float4*)&images[base + 4 * k];
        float4 ev = make_float4(iv.x - ra.x, iv.y - ra.y, iv.z - rb.x, iv.w - rb.y);
        *(float4*)&g_e[base + 4 * k] = ev;
    }
}

// ---------------------------------------------------------------------------
// conv + Adam fused (unchanged from round 4).
// Block 128 thr, tile oy:8 x ox:32 x 16 channels, one batch.
// Thread: 4 ox x 8 ch = 16 f32x2 accumulators.
// ---------------------------------------------------------------------------
__global__ __launch_bounds__(128) void conv_adam_kernel(
    const float* __restrict__ images, const float* __restrict__ filt,
    float* __restrict__ out, int t, float c1, float c2, int use_e)
{
    __shared__ __align__(16) float sF[16 * 16 * 16];  // 16 KB
    __shared__ __align__(16) float sImg[44 * 156];    // 27.4 KB

    const float* __restrict__ src = use_e ? (const float*)g_e : images;

    const int tid = threadIdx.x;
    const int b   = blockIdx.z >> 2;
    const int c0  = (blockIdx.z & 3) * 16;
    const int oy0 = blockIdx.y * 8;
    const int ox0 = blockIdx.x * 32;

    for (int i = tid * 4; i < 16 * 16 * 16; i += 512) {
        int kxy = i >> 4;
        int c_l = i & 15;
        *(float4*)&sF[i] = *(const float4*)&filt[kxy * 64 + c0 + c_l];
    }
    for (int idx = tid; idx < 44 * 140; idx += 128) {
        int rr = idx / 140;
        int cc = idx - rr * 140;
        int r = 4 * oy0 + rr;
        int q = 4 * ox0 + cc;
        float v = (r < HH && q < WW) ? src[(b * HH + r) * WW + q] : 0.f;
        sImg[rr * 156 + cc + ((cc >> 5) << 2)] = v;
    }
    __syncthreads();

    const int cg   = tid & 1;          // ch subgroup: c0 + 8*cg .. +7
    const int oxp  = (tid >> 1) & 7;   // 4 ox: ox0 + 4*oxp .. +3
    const int oy_l = tid >> 4;         // 0..7

    ull A[4][4];                        // [ox][ch-pair]
#pragma unroll
    for (int x = 0; x < 4; x++)
#pragma unroll
        for (int p = 0; p < 4; p++) A[x][p] = 0ull;

#pragma unroll 1
    for (int ky = 0; ky < 16; ky++) {
        const float* row = &sImg[(4 * oy_l + ky) * 156];
        float w[28];
#pragma unroll
        for (int x = 0; x < 7; x++) {
            int cc = 16 * oxp + 4 * x;
            int pc = cc + ((cc >> 5) << 2);
            float4 t4 = *(const float4*)&row[pc];
            w[4 * x + 0] = t4.x; w[4 * x + 1] = t4.y;
            w[4 * x + 2] = t4.z; w[4 * x + 3] = t4.w;
        }
#pragma unroll
        for (int kx = 0; kx < 16; kx++) {
            const ulonglong2* fp = (const ulonglong2*)&sF[(ky * 16 + kx) * 16 + cg * 8];
            ulonglong2 fa = fp[0];
            ulonglong2 fb = fp[1];
#pragma unroll
            for (int x = 0; x < 4; x++) {
                ull iv = bcast2(w[kx + 4 * x]);
                A[x][0] = ffma2(iv, fa.x, A[x][0]);
                A[x][1] = ffma2(iv, fa.y, A[x][1]);
                A[x][2] = ffma2(iv, fb.x, A[x][2]);
                A[x][3] = ffma2(iv, fb.y, A[x][3]);
            }
        }
    }

    const int oy = oy0 + oy_l;
    if (oy > 60) return;

#pragma unroll
    for (int x = 0; x < 4; x++) {
        int ox = ox0 + 4 * oxp + x;
        if (ox > 60) continue;
        int base = ((b * SPAT + oy * OHW + ox) << 6) + c0 + (cg << 3);

        float cv[8];
#pragma unroll
        for (int p = 0; p < 4; p++) {
            float2 r = unpack2(A[x][p]);
            cv[2 * p]     = r.x;
            cv[2 * p + 1] = r.y;
        }
        float un[8], mn[8], vn[8];
        if (t == 1) {
#pragma unroll
            for (int k = 0; k < 8; k++) {
                float g = cv[k];
                mn[k] = OMB1 * g;
                vn[k] = OMB2 * g * g;
                un[k] = LR * (mn[k] * c1) / (sqrtf(vn[k] * c2) + EPSc);
            }
        } else {
            float4 u0 = *(const float4*)&g_u[base];
            float4 u1 = *(const float4*)&g_u[base + 4];
            float4 m0 = *(const float4*)&g_m[base];
            float4 m1 = *(const float4*)&g_m[base + 4];
            float4 v0 = *(const float4*)&g_v[base];
            float4 v1 = *(const float4*)&g_v[base + 4];
            float uo[8] = {u0.x, u0.y, u0.z, u0.w, u1.x, u1.y, u1.z, u1.w};
            float mo[8] = {m0.x, m0.y, m0.z, m0.w, m1.x, m1.y, m1.z, m1.w};
            float vo[8] = {v0.x, v0.y, v0.z, v0.w, v1.x, v1.y, v1.z, v1.w};
#pragma unroll
            for (int k = 0; k < 8; k++) {
                float act = fmaxf(uo[k] - LAM, 0.f);
                float g   = cv[k] - uo[k] + act;
                mn[k] = B1c * mo[k] + OMB1 * g;
                vn[k] = B2c * vo[k] + OMB2 * g * g;
                un[k] = uo[k] + LR * (mn[k] * c1) / (sqrtf(vn[k] * c2) + EPSc);
            }
        }

        if (t == 10) {
            float4 o0 = make_float4(fmaxf(un[0] - LAM, 0.f), fmaxf(un[1] - LAM, 0.f),
                                    fmaxf(un[2] - LAM, 0.f), fmaxf(un[3] - LAM, 0.f));
            float4 o1 = make_float4(fmaxf(un[4] - LAM, 0.f), fmaxf(un[5] - LAM, 0.f),
                                    fmaxf(un[6] - LAM, 0.f), fmaxf(un[7] - LAM, 0.f));
            *(float4*)&out[base]     = o0;
            *(float4*)&out[base + 4] = o1;
        } else {
            *(float4*)&g_u[base]     = make_float4(un[0], un[1], un[2], un[3]);
            *(float4*)&g_u[base + 4] = make_float4(un[4], un[5], un[6], un[7]);
            *(float4*)&g_m[base]     = make_float4(mn[0], mn[1], mn[2], mn[3]);
            *(float4*)&g_m[base + 4] = make_float4(mn[4], mn[5], mn[6], mn[7]);
            *(float4*)&g_v[base]     = make_float4(vn[0], vn[1], vn[2], vn[3]);
            *(float4*)&g_v[base + 4] = make_float4(vn[4], vn[5], vn[6], vn[7]);
        }
    }
}

// ---------------------------------------------------------------------------
// launcher: 1 prep + 1 init + 9 x (recon + conv_adam), graph-capturable.
// ---------------------------------------------------------------------------
extern "C" void kernel_launch(void* const* d_in, const int* in_sizes, int n_in,
                              void* d_out, int out_size)
{
    const float* images = (const float*)d_in[0];
    const float* filt   = (const float*)d_in[1];
    if (n_in >= 2 && in_sizes[0] == 16 * 16 * 64) {
        images = (const float*)d_in[1];
        filt   = (const float*)d_in[0];
    }
    float* out = (float*)d_out;

    prep_filt_kernel<<<64, 256>>>(filt);

    dim3 gridC(2, 8, 128);  // ox tiles, oy tiles, b*4 channel quarters
    dim3 gridR(4, 8, 32);   // g tiles (16 cells), a tiles (8 cells), b

    conv_adam_kernel<<<gridC, 128>>>(images, filt, out, 1, 10.0f, 100.0f, 0);

    for (int t = 2; t <= 10; t++) {
        double c1 = 1.0 / (1.0 - pow(0.9,  (double)t));
        double c2 = 1.0 / (1.0 - pow(0.99, (double)t));
        recon_kernel<<<gridR, 128>>>(images);
        conv_adam_kernel<<<gridC, 128>>>(images, filt, out, t, (float)c1, (float)c2, 1);
    }
}